// round 8
// baseline (speedup 1.0000x reference)
#include <cuda_runtime.h>
#include <math.h>
#include <stdint.h>

#define NACC_MAX 200000
#define NMER_MAX 100000
#define E_MAX    500000

// ---------------- scratch (device globals; no allocations allowed) -------------
__device__ float g_xa[(size_t)NACC_MAX * 128];
__device__ float g_xm[(size_t)NMER_MAX * 128];
__device__ float g_ya[(size_t)NACC_MAX * 128];
__device__ float g_ym[(size_t)NMER_MAX * 128];
__device__ float g_agg[(size_t)NACC_MAX * 128];   // rev -> acc
__device__ float g_agg2[(size_t)NACC_MAX * 128];  // transfer -> acc
__device__ float g_aggm[(size_t)NMER_MAX * 128];  // pays -> mer
__device__ int   g_rowptr[3][NACC_MAX + 1];
__device__ int   g_csr[3][E_MAX];
__device__ int   g_deg[NACC_MAX];
__device__ int   g_cur[NACC_MAX];
__device__ int   g_bsum[1024];
// stats: [accP0 sum|sqs][accP1 sum|sqs][merP0 sum|sqs][merP1 sum|sqs]
__device__ float g_stat[8 * 128];

// ---------------- bf16x3 emulation helpers ---------------------------------------
__device__ __forceinline__ void split2(float2 v, uint32_t& h, uint32_t& l) {
    uint32_t u0 = __float_as_uint(v.x), u1 = __float_as_uint(v.y);
    h = __byte_perm(u0, u1, 0x7632);
    float r0 = v.x - __uint_as_float(u0 & 0xFFFF0000u);
    float r1 = v.y - __uint_as_float(u1 & 0xFFFF0000u);
    asm("cvt.rn.bf16x2.f32 %0, %1, %2;" : "=r"(l) : "f"(r1), "f"(r0));
}

__device__ __forceinline__ void mma_bf16(float* d, const uint32_t* a,
                                         uint32_t b0, uint32_t b1) {
    asm volatile(
        "mma.sync.aligned.m16n8k16.row.col.f32.bf16.bf16.f32 "
        "{%0,%1,%2,%3}, {%4,%5,%6,%7}, {%8,%9}, {%0,%1,%2,%3};"
        : "+f"(d[0]), "+f"(d[1]), "+f"(d[2]), "+f"(d[3])
        : "r"(a[0]), "r"(a[1]), "r"(a[2]), "r"(a[3]), "r"(b0), "r"(b1));
}

__device__ __forceinline__ uint32_t saddr(const void* p) {
    uint32_t a;
    asm("{ .reg .u64 t; cvta.to.shared.u64 t, %1; cvt.u32.u64 %0, t; }"
        : "=r"(a) : "l"(p));
    return a;
}

__device__ __forceinline__ void cp16(uint32_t dst, const void* src, bool pred) {
    asm volatile("cp.async.cg.shared.global [%0], [%1], 16, %2;"
                 :: "r"(dst), "l"(src), "r"(pred ? 16 : 0) : "memory");
}
__device__ __forceinline__ void cp_commit() {
    asm volatile("cp.async.commit_group;" ::: "memory");
}

// ---------------- CSR build ------------------------------------------------------
__global__ void hist_kernel(const int* __restrict__ ei, int E, int* __restrict__ deg) {
    int e = blockIdx.x * blockDim.x + threadIdx.x;
    if (e >= E) return;
    atomicAdd(&deg[ei[E + e]], 1);
}

__global__ void scan1(const int* __restrict__ deg, int n,
                      int* __restrict__ rowptr, int* __restrict__ bsum) {
    __shared__ int s[1024];
    int i = blockIdx.x * 1024 + threadIdx.x;
    int v = (i < n) ? deg[i] : 0;
    s[threadIdx.x] = v;
    __syncthreads();
    for (int off = 1; off < 1024; off <<= 1) {
        int t = (threadIdx.x >= off) ? s[threadIdx.x - off] : 0;
        __syncthreads();
        s[threadIdx.x] += t;
        __syncthreads();
    }
    if (i < n) rowptr[i + 1] = s[threadIdx.x];
    if (threadIdx.x == 1023) bsum[blockIdx.x] = s[1023];
}

__global__ void scan2(int* __restrict__ bsum, int nb) {
    __shared__ int s[1024];
    int v = (threadIdx.x < nb) ? bsum[threadIdx.x] : 0;
    s[threadIdx.x] = v;
    __syncthreads();
    for (int off = 1; off < 1024; off <<= 1) {
        int t = (threadIdx.x >= off) ? s[threadIdx.x - off] : 0;
        __syncthreads();
        s[threadIdx.x] += t;
        __syncthreads();
    }
    if (threadIdx.x < nb) bsum[threadIdx.x] = s[threadIdx.x] - v;  // exclusive
}

__global__ void scan3(int n, int* __restrict__ rowptr, const int* __restrict__ bsum) {
    int i = blockIdx.x * blockDim.x + threadIdx.x;
    if (i < n) rowptr[i + 1] += bsum[i >> 10];
    if (i == 0) rowptr[0] = 0;
}

__global__ void scatter_kernel(const int* __restrict__ ei, int E,
                               int* __restrict__ cur, int* __restrict__ csr) {
    int e = blockIdx.x * blockDim.x + threadIdx.x;
    if (e >= E) return;
    int src = ei[e], dst = ei[E + e];
    int pos = atomicAdd(&cur[dst], 1);
    csr[pos] = src;
}

// ---------------- fused mean aggregation with on-the-fly BN+ReLU ----------------
struct SegParams {
    int n;
    const int* rp; const int* cs;
    const float* src; float* out;
    const float* sum; const float* sqs;   // nullptr -> identity (no BN)
    const float* g; const float* b;
    float invn; int relu;
};

__global__ __launch_bounds__(256)
void agg_all(SegParams s0, SegParams s1, SegParams s2)
{
    int w = (blockIdx.x * blockDim.x + threadIdx.x) >> 5;
    int lane = threadIdx.x & 31;
    const SegParams* S; int d;
    if (w < s0.n)                { S = &s0; d = w; }
    else if (w < s0.n + s1.n)    { S = &s1; d = w - s0.n; }
    else if (w < s0.n + s1.n + s2.n) { S = &s2; d = w - s0.n - s1.n; }
    else return;

    float4 sc = make_float4(1.f, 1.f, 1.f, 1.f);
    float4 sh = make_float4(0.f, 0.f, 0.f, 0.f);
    if (S->sum) {
        float4 sm4 = __ldg(reinterpret_cast<const float4*>(S->sum) + lane);
        float4 sq4 = __ldg(reinterpret_cast<const float4*>(S->sqs) + lane);
        float4 g4  = __ldg(reinterpret_cast<const float4*>(S->g) + lane);
        float4 b4  = __ldg(reinterpret_cast<const float4*>(S->b) + lane);
        float invn = S->invn;
#pragma unroll
        for (int c = 0; c < 4; c++) {
            float mu = (&sm4.x)[c] * invn;
            float var = (&sq4.x)[c] * invn - mu * mu;
            float iv = rsqrtf(var + 1e-5f);
            float s = (&g4.x)[c] * iv;
            (&sc.x)[c] = s;
            (&sh.x)[c] = (&b4.x)[c] - mu * s;
        }
    }
    int relu = S->relu;

    int s = __ldg(&S->rp[d]), e = __ldg(&S->rp[d + 1]);
    const float* src = S->src;
    const int* cs = S->cs;
    float4 acc = make_float4(0.f, 0.f, 0.f, 0.f);
    for (int i = s; i < e; i++) {
        int s0i = __ldg(&cs[i]);
        float4 v = __ldg(reinterpret_cast<const float4*>(src + (size_t)s0i * 128) + lane);
        v.x = v.x * sc.x + sh.x; v.y = v.y * sc.y + sh.y;
        v.z = v.z * sc.z + sh.z; v.w = v.w * sc.w + sh.w;
        if (relu) {
            v.x = fmaxf(v.x, 0.f); v.y = fmaxf(v.y, 0.f);
            v.z = fmaxf(v.z, 0.f); v.w = fmaxf(v.w, 0.f);
        }
        acc.x += v.x; acc.y += v.y; acc.z += v.z; acc.w += v.w;
    }
    float inv = 1.f / fmaxf((float)(e - s), 1.f);
    acc.x *= inv; acc.y *= inv; acc.z *= inv; acc.w *= inv;
    *(reinterpret_cast<float4*>(S->out + (size_t)d * 128) + lane) = acc;
}

// ---------------- bf16x3 pipelined GEMM (512 threads, R5 shape) -----------------
// D[128, DO] per CTA = A[128, K] @ B[DO, K]^T
// MODE 0: A = A1[n,K] raw (input projection), epilogue = +bias.
// MODE 1: K=256, A = [mean_agg | bn_relu(ydst)] with BN applied on the fly to the
//         k>=128 fragments. Epilogue = +bias, row L2-norm, optional += (HeteroConv).
// STATS : fused BatchNorm column sum/sumsq of the final output values.
// 512 threads = 16 warps, 4(m) x 4(n); warp tile 32m x (DO/4)n; BK=16, cp.async x2.
template<int DO, int MODE, bool ACCUM, bool STATS>
__global__ __launch_bounds__(512)
void mma_gemm(int n, int K,
              const float* __restrict__ A1, const float* __restrict__ A2,
              const float* __restrict__ B1, const float* __restrict__ B2,
              const float* __restrict__ bias, float* __restrict__ C,
              float* __restrict__ gsum, float* __restrict__ gsqs,
              const float* __restrict__ psum, const float* __restrict__ psqs,
              const float* __restrict__ pg, const float* __restrict__ pb,
              float pinvn, int prelu)
{
    constexpr int NJ = DO / 32;
    __shared__ float As[2][128][20];
    __shared__ float Bs[2][128][20];
    __shared__ float sBias[128];
    __shared__ float sSc[128], sSh[128];
    __shared__ float ssRow[128];
    __shared__ float sCS[128], sCQ[128];

    int tid = threadIdx.x, lane = tid & 31, warp = tid >> 5;
    int g = lane >> 2, t = lane & 3;
    int wm = warp & 3, wn = warp >> 2;
    int row0 = blockIdx.x * 128;

    if (tid < DO) {
        sBias[tid] = bias[tid];
        if (STATS) { sCS[tid] = 0.f; sCQ[tid] = 0.f; }
    }
    if (tid < 128) {
        ssRow[tid] = 0.f;
        if (MODE == 1) {
            float sc = 1.f, sh = 0.f;
            if (psum) {
                float mu = psum[tid] * pinvn;
                float var = psqs[tid] * pinvn - mu * mu;
                float iv = rsqrtf(var + 1e-5f);
                sc = pg[tid] * iv;
                sh = pb[tid] - mu * sc;
            }
            sSc[tid] = sc; sSh[tid] = sh;
        }
    }

    float acc[2][NJ][4];
#pragma unroll
    for (int i = 0; i < 2; i++)
#pragma unroll
        for (int j = 0; j < NJ; j++)
#pragma unroll
            for (int c = 0; c < 4; c++) acc[i][j][c] = 0.f;

    const int T = K >> 4;

    auto load_tile = [&](int kt, int buf) {
        {   // A tile 128x16: one float4 per thread
            int m = tid >> 2, q = tid & 3, k = kt * 16 + q * 4;
            int r = row0 + m;
            bool p = (r < n);
            int rc = p ? r : 0;
            const float* src;
            if (MODE == 0) src = A1 + (size_t)rc * K + k;
            else src = (k < 128) ? A1 + (size_t)rc * 128 + k
                                 : A2 + (size_t)rc * 128 + (k - 128);
            cp16(saddr(&As[buf][m][q * 4]), src, p);
        }
        if (tid < DO * 4) {  // B tile: DO*4 float4 <= 512 threads
            int j = tid >> 2, q = tid & 3, k = kt * 16 + q * 4;
            const float* src;
            if (MODE == 1) src = (k < 128) ? B1 + (size_t)j * 128 + k
                                           : B2 + (size_t)j * 128 + (k - 128);
            else src = B1 + (size_t)j * K + k;
            cp16(saddr(&Bs[buf][j][q * 4]), src, true);
        }
    };

    auto compute = [&](int kt, int buf) {
        bool tr = (MODE == 1) && (kt >= 8);
        float2 sca, scb, sha, shb;
        if (tr) {
            int kb = (kt - 8) * 16;
            sca = *reinterpret_cast<const float2*>(&sSc[kb + 2 * t]);
            scb = *reinterpret_cast<const float2*>(&sSc[kb + 2 * t + 8]);
            sha = *reinterpret_cast<const float2*>(&sSh[kb + 2 * t]);
            shb = *reinterpret_cast<const float2*>(&sSh[kb + 2 * t + 8]);
        }
        // B fragments hoisted across the i-loop
        uint32_t bh[NJ][2], bl[NJ][2];
#pragma unroll
        for (int j = 0; j < NJ; j++) {
            int nb = wn * (NJ * 8) + j * 8 + g;
            float2 w0 = *reinterpret_cast<const float2*>(&Bs[buf][nb][2 * t]);
            float2 w1 = *reinterpret_cast<const float2*>(&Bs[buf][nb][2 * t + 8]);
            split2(w0, bh[j][0], bl[j][0]);
            split2(w1, bh[j][1], bl[j][1]);
        }
#pragma unroll
        for (int i = 0; i < 2; i++) {
            int rb = wm * 32 + i * 16;
            float2 v0 = *reinterpret_cast<const float2*>(&As[buf][rb + g][2 * t]);
            float2 v1 = *reinterpret_cast<const float2*>(&As[buf][rb + g + 8][2 * t]);
            float2 v2 = *reinterpret_cast<const float2*>(&As[buf][rb + g][2 * t + 8]);
            float2 v3 = *reinterpret_cast<const float2*>(&As[buf][rb + g + 8][2 * t + 8]);
            if (tr) {
                v0.x = v0.x * sca.x + sha.x; v0.y = v0.y * sca.y + sha.y;
                v1.x = v1.x * sca.x + sha.x; v1.y = v1.y * sca.y + sha.y;
                v2.x = v2.x * scb.x + shb.x; v2.y = v2.y * scb.y + shb.y;
                v3.x = v3.x * scb.x + shb.x; v3.y = v3.y * scb.y + shb.y;
                if (prelu) {
                    v0.x = fmaxf(v0.x, 0.f); v0.y = fmaxf(v0.y, 0.f);
                    v1.x = fmaxf(v1.x, 0.f); v1.y = fmaxf(v1.y, 0.f);
                    v2.x = fmaxf(v2.x, 0.f); v2.y = fmaxf(v2.y, 0.f);
                    v3.x = fmaxf(v3.x, 0.f); v3.y = fmaxf(v3.y, 0.f);
                }
            }
            uint32_t ah[4], al[4];
            split2(v0, ah[0], al[0]);
            split2(v1, ah[1], al[1]);
            split2(v2, ah[2], al[2]);
            split2(v3, ah[3], al[3]);
#pragma unroll
            for (int j = 0; j < NJ; j++) {
                mma_bf16(acc[i][j], ah, bh[j][0], bh[j][1]);
                mma_bf16(acc[i][j], ah, bl[j][0], bl[j][1]);
                mma_bf16(acc[i][j], al, bh[j][0], bh[j][1]);
            }
        }
    };

    // 2-stage pipeline (R5 proven shape)
    load_tile(0, 0);
    cp_commit();
    for (int kt = 0; kt < T; kt++) {
        if (kt + 1 < T) { load_tile(kt + 1, (kt + 1) & 1); cp_commit(); }
        if (kt + 1 < T) asm volatile("cp.async.wait_group 1;" ::: "memory");
        else            asm volatile("cp.async.wait_group 0;" ::: "memory");
        __syncthreads();
        compute(kt, kt & 1);
        __syncthreads();
    }

    // ---- epilogue: bias, row L2-norm, accumulate, fused BN stats ----
#pragma unroll
    for (int i = 0; i < 2; i++) {
        float ss0 = 0.f, ss1 = 0.f;
#pragma unroll
        for (int j = 0; j < NJ; j++) {
            int cb = wn * (NJ * 8) + j * 8 + t * 2;
            float b0 = sBias[cb], b1 = sBias[cb + 1];
            acc[i][j][0] += b0; acc[i][j][1] += b1;
            acc[i][j][2] += b0; acc[i][j][3] += b1;
            if (MODE == 1) {
                ss0 += acc[i][j][0] * acc[i][j][0] + acc[i][j][1] * acc[i][j][1];
                ss1 += acc[i][j][2] * acc[i][j][2] + acc[i][j][3] * acc[i][j][3];
            }
        }
        if (MODE == 1) {
            ss0 += __shfl_xor_sync(0xffffffffu, ss0, 1);
            ss0 += __shfl_xor_sync(0xffffffffu, ss0, 2);
            ss1 += __shfl_xor_sync(0xffffffffu, ss1, 1);
            ss1 += __shfl_xor_sync(0xffffffffu, ss1, 2);
            if (t == 0) {
                atomicAdd(&ssRow[wm * 32 + i * 16 + g], ss0);
                atomicAdd(&ssRow[wm * 32 + i * 16 + g + 8], ss1);
            }
        }
    }
    __syncthreads();

    float cs[NJ][2], cq[NJ][2];
    if (STATS) {
#pragma unroll
        for (int j = 0; j < NJ; j++) { cs[j][0] = cs[j][1] = cq[j][0] = cq[j][1] = 0.f; }
    }

#pragma unroll
    for (int i = 0; i < 2; i++) {
        int rl = wm * 32 + i * 16 + g;
        float s0 = 1.f, s1 = 1.f;
        if (MODE == 1) {
            s0 = 1.f / fmaxf(sqrtf(ssRow[rl]), 1e-12f);
            s1 = 1.f / fmaxf(sqrtf(ssRow[rl + 8]), 1e-12f);
        }
        int r0 = row0 + rl, r1 = r0 + 8;
#pragma unroll
        for (int j = 0; j < NJ; j++) {
            int cb = wn * (NJ * 8) + j * 8 + t * 2;
            if (r0 < n) {
                float2* p = reinterpret_cast<float2*>(C + (size_t)r0 * DO + cb);
                float2 v = make_float2(acc[i][j][0] * s0, acc[i][j][1] * s0);
                if (ACCUM) { float2 o = *p; v.x += o.x; v.y += o.y; }
                *p = v;
                if (STATS) {
                    cs[j][0] += v.x; cs[j][1] += v.y;
                    cq[j][0] += v.x * v.x; cq[j][1] += v.y * v.y;
                }
            }
            if (r1 < n) {
                float2* p = reinterpret_cast<float2*>(C + (size_t)r1 * DO + cb);
                float2 v = make_float2(acc[i][j][2] * s1, acc[i][j][3] * s1);
                if (ACCUM) { float2 o = *p; v.x += o.x; v.y += o.y; }
                *p = v;
                if (STATS) {
                    cs[j][0] += v.x; cs[j][1] += v.y;
                    cq[j][0] += v.x * v.x; cq[j][1] += v.y * v.y;
                }
            }
        }
    }

    if (STATS) {
#pragma unroll
        for (int j = 0; j < NJ; j++)
#pragma unroll
            for (int c = 0; c < 2; c++) {
                float s = cs[j][c], q = cq[j][c];
                s += __shfl_xor_sync(0xffffffffu, s, 4);
                s += __shfl_xor_sync(0xffffffffu, s, 8);
                s += __shfl_xor_sync(0xffffffffu, s, 16);
                q += __shfl_xor_sync(0xffffffffu, q, 4);
                q += __shfl_xor_sync(0xffffffffu, q, 8);
                q += __shfl_xor_sync(0xffffffffu, q, 16);
                if (g == 0) {
                    int cb = wn * (NJ * 8) + j * 8 + t * 2 + c;
                    atomicAdd(&sCS[cb], s);
                    atomicAdd(&sCQ[cb], q);
                }
            }
        __syncthreads();
        if (tid < DO) {
            atomicAdd(&gsum[tid], sCS[tid]);
            atomicAdd(&gsqs[tid], sCQ[tid]);
        }
    }
}

// ---------------- classifier with fused final BN (no relu) ----------------------
__global__ __launch_bounds__(256)
void classifier_kernel(const float* __restrict__ X, int n,
                       const float* __restrict__ W1, const float* __restrict__ b1,
                       const float* __restrict__ W2, const float* __restrict__ b2,
                       float* __restrict__ out,
                       const float* __restrict__ psum, const float* __restrict__ psqs,
                       const float* __restrict__ pg, const float* __restrict__ pb,
                       float pinvn)
{
    __shared__ float sW1[64 * 65];
    __shared__ float sW2[64];
    __shared__ float sb1[64];
    __shared__ float ssc[64], ssh[64];
    int tid = threadIdx.x;
    for (int i = tid; i < 64 * 64; i += 256) {
        int j = i >> 6, k = i & 63;
        sW1[j * 65 + k] = W1[i];
    }
    if (tid < 64) {
        sW2[tid] = W2[tid]; sb1[tid] = b1[tid];
        float mu = psum[tid] * pinvn;
        float var = psqs[tid] * pinvn - mu * mu;
        float iv = rsqrtf(var + 1e-5f);
        float sc = pg[tid] * iv;
        ssc[tid] = sc;
        ssh[tid] = pb[tid] - mu * sc;
    }
    __syncthreads();

    int lane = tid & 31;
    int row = blockIdx.x * 8 + (tid >> 5);
    if (row >= n) return;
    float x0 = X[(size_t)row * 64 + lane] * ssc[lane] + ssh[lane];
    float x1 = X[(size_t)row * 64 + 32 + lane] * ssc[lane + 32] + ssh[lane + 32];
    float h0 = sb1[lane], h1 = sb1[lane + 32];
#pragma unroll
    for (int k = 0; k < 32; k++) {
        float xk = __shfl_sync(0xffffffffu, x0, k);
        h0 += xk * sW1[lane * 65 + k];
        h1 += xk * sW1[(lane + 32) * 65 + k];
    }
#pragma unroll
    for (int k = 0; k < 32; k++) {
        float xk = __shfl_sync(0xffffffffu, x1, k);
        h0 += xk * sW1[lane * 65 + 32 + k];
        h1 += xk * sW1[(lane + 32) * 65 + 32 + k];
    }
    h0 = fmaxf(h0, 0.f); h1 = fmaxf(h1, 0.f);
    float p = h0 * sW2[lane] + h1 * sW2[lane + 32];
#pragma unroll
    for (int off = 16; off; off >>= 1)
        p += __shfl_xor_sync(0xffffffffu, p, off);
    if (lane == 0) out[row] = p + b2[0];
}

// ---------------- host-side CSR build --------------------------------------------
static void build_csr(const int* ei, int E, int ndst,
                      int* rowptr, int* csr, int* deg, int* cur, int* bsum)
{
    cudaMemsetAsync(deg, 0, (size_t)ndst * sizeof(int), 0);
    hist_kernel<<<(E + 255) / 256, 256>>>(ei, E, deg);
    int nb = (ndst + 1023) / 1024;
    scan1<<<nb, 1024>>>(deg, ndst, rowptr, bsum);
    scan2<<<1, 1024>>>(bsum, nb);
    scan3<<<(ndst + 255) / 256, 256>>>(ndst, rowptr, bsum);
    cudaMemcpyAsync(cur, rowptr, (size_t)ndst * sizeof(int),
                    cudaMemcpyDeviceToDevice, 0);
    scatter_kernel<<<(E + 255) / 256, 256>>>(ei, E, cur, csr);
}

// ---------------- kernel_launch -------------------------------------------------
extern "C" void kernel_launch(void* const* d_in, const int* in_sizes, int n_in,
                              void* d_out, int out_size)
{
    const float* x_acc      = (const float*)d_in[0];
    const float* x_mer      = (const float*)d_in[1];
    const int*   ei_pays    = (const int*)d_in[2];
    const int*   ei_rev     = (const int*)d_in[3];
    const int*   ei_tr      = (const int*)d_in[4];
    const float* projW_acc  = (const float*)d_in[5];
    const float* projb_acc  = (const float*)d_in[6];
    const float* projW_mer  = (const float*)d_in[7];
    const float* projb_mer  = (const float*)d_in[8];
    const float* Wl[3] = {(const float*)d_in[9],  (const float*)d_in[12], (const float*)d_in[15]};
    const float* bl[3] = {(const float*)d_in[10], (const float*)d_in[13], (const float*)d_in[16]};
    const float* Wr[3] = {(const float*)d_in[11], (const float*)d_in[14], (const float*)d_in[17]};
    const float* bng[3] = {(const float*)d_in[18], (const float*)d_in[20], (const float*)d_in[22]};
    const float* bnb[3] = {(const float*)d_in[19], (const float*)d_in[21], (const float*)d_in[23]};
    const float* clfW1 = (const float*)d_in[24];
    const float* clfb1 = (const float*)d_in[25];
    const float* clfW2 = (const float*)d_in[26];
    const float* clfb2 = (const float*)d_in[27];
    float* out = (float*)d_out;

    int nacc = in_sizes[0] / 64;
    int nmer = in_sizes[1] / 32;
    int E    = in_sizes[2] / 2;
    float invA = 1.f / (float)nacc, invM = 1.f / (float)nmer;

    float *xa, *xm, *ya, *ym, *agg, *agg2, *aggm, *stat;
    int *rowptr, *csr, *deg, *cur, *bsum;
    cudaGetSymbolAddress((void**)&xa,     g_xa);
    cudaGetSymbolAddress((void**)&xm,     g_xm);
    cudaGetSymbolAddress((void**)&ya,     g_ya);
    cudaGetSymbolAddress((void**)&ym,     g_ym);
    cudaGetSymbolAddress((void**)&agg,    g_agg);
    cudaGetSymbolAddress((void**)&agg2,   g_agg2);
    cudaGetSymbolAddress((void**)&aggm,   g_aggm);
    cudaGetSymbolAddress((void**)&stat,   g_stat);
    cudaGetSymbolAddress((void**)&rowptr, g_rowptr);
    cudaGetSymbolAddress((void**)&csr,    g_csr);
    cudaGetSymbolAddress((void**)&deg,    g_deg);
    cudaGetSymbolAddress((void**)&cur,    g_cur);
    cudaGetSymbolAddress((void**)&bsum,   g_bsum);

    int* rp[3]  = {rowptr, rowptr + (NACC_MAX + 1), rowptr + 2 * (NACC_MAX + 1)};
    int* cs3[3] = {csr, csr + E_MAX, csr + 2 * E_MAX};
    float* stA[2] = {stat, stat + 256};          // [sum|sqs] per parity
    float* stM[2] = {stat + 512, stat + 768};

    // --- CSR builds (one per edge type, reused across layers) ---
    build_csr(ei_pays, E, nmer, rp[0], cs3[0], deg, cur, bsum);
    build_csr(ei_rev,  E, nacc, rp[1], cs3[1], deg, cur, bsum);
    build_csr(ei_tr,   E, nacc, rp[2], cs3[2], deg, cur, bsum);

    int agrid = (nacc + 127) / 128;
    int mgrid = (nmer + 127) / 128;

    // --- input projections (raw linear, no BN) ---
    mma_gemm<128, 0, false, false><<<agrid, 512>>>(nacc, 64, x_acc, nullptr,
        projW_acc, nullptr, projb_acc, xa, nullptr, nullptr,
        nullptr, nullptr, nullptr, nullptr, 0.f, 0);
    mma_gemm<128, 0, false, false><<<mgrid, 512>>>(nmer, 32, x_mer, nullptr,
        projW_mer, nullptr, projb_mer, xm, nullptr, nullptr,
        nullptr, nullptr, nullptr, nullptr, 0.f, 0);

    // ping-pong feature buffers (pre-BN), stats carried separately
    float* accSrc[3] = {xa, ya, xa};
    float* accDst[3] = {ya, xa, ya};
    float* merSrc[3] = {xm, ym, xm};
    float* merDst[3] = {ym, xm, nullptr};

    int douts[3] = {128, 128, 64};
    for (int L = 0; L < 3; L++) {
        int DO = douts[L];
        int pL = L & 1;
        const float* pAs = (L > 0) ? stA[(L - 1) & 1] : nullptr;
        const float* pAq = pAs ? pAs + 128 : nullptr;
        const float* pMs = (L > 0) ? stM[(L - 1) & 1] : nullptr;
        const float* pMq = pMs ? pMs + 128 : nullptr;
        const float* gA = (L > 0) ? bng[L - 1] + 0 : nullptr;
        const float* bA = (L > 0) ? bnb[L - 1] + 0 : nullptr;
        const float* gM = (L > 0) ? bng[L - 1] + 128 : nullptr;
        const float* bM = (L > 0) ? bnb[L - 1] + 128 : nullptr;
        int relu = (L > 0) ? 1 : 0;
        int n0 = (L < 2) ? nmer : 0;   // pays dead at L==2

        // --- all aggregations for this layer in one launch (BN+ReLU on the fly) ---
        SegParams s0 = {n0,   rp[0], cs3[0], accSrc[L], aggm, pAs, pAq, gA, bA, invA, relu};
        SegParams s1 = {nacc, rp[1], cs3[1], merSrc[L], agg,  pMs, pMq, gM, bM, invM, relu};
        SegParams s2 = {nacc, rp[2], cs3[2], accSrc[L], agg2, pAs, pAq, gA, bA, invA, relu};
        int twarp = n0 + nacc + nacc;
        agg_all<<<(twarp * 32 + 255) / 256, 256>>>(s0, s1, s2);

        // (a) pays: acc -> mer; emits merchant BN stats
        if (L < 2) {
            cudaMemsetAsync(stM[pL], 0, 256 * sizeof(float), 0);
            mma_gemm<128, 1, false, true><<<mgrid, 512>>>(nmer, 256, aggm,
                merSrc[L],
                Wl[L] + 0 * (size_t)DO * 128, Wr[L] + 0 * (size_t)DO * 128,
                bl[L] + 0 * DO, merDst[L], stM[pL], stM[pL] + 128,
                pMs, pMq, gM, bM, invM, relu);
        }

        // (b) rev: mer -> acc (no stats: not final value yet)
        if (DO == 128)
            mma_gemm<128, 1, false, false><<<agrid, 512>>>(nacc, 256, agg,
                accSrc[L],
                Wl[L] + 1 * (size_t)DO * 128, Wr[L] + 1 * (size_t)DO * 128,
                bl[L] + 1 * DO, accDst[L], nullptr, nullptr,
                pAs, pAq, gA, bA, invA, relu);
        else
            mma_gemm<64, 1, false, false><<<agrid, 512>>>(nacc, 256, agg,
                accSrc[L],
                Wl[L] + 1 * (size_t)DO * 128, Wr[L] + 1 * (size_t)DO * 128,
                bl[L] + 1 * DO, accDst[L], nullptr, nullptr,
                pAs, pAq, gA, bA, invA, relu);

        // (c) transfer: acc -> acc (HeteroConv +=); emits account BN stats
        cudaMemsetAsync(stA[pL], 0, 256 * sizeof(float), 0);
        if (DO == 128)
            mma_gemm<128, 1, true, true><<<agrid, 512>>>(nacc, 256, agg2,
                accSrc[L],
                Wl[L] + 2 * (size_t)DO * 128, Wr[L] + 2 * (size_t)DO * 128,
                bl[L] + 2 * DO, accDst[L], stA[pL], stA[pL] + 128,
                pAs, pAq, gA, bA, invA, relu);
        else
            mma_gemm<64, 1, true, true><<<agrid, 512>>>(nacc, 256, agg2,
                accSrc[L],
                Wl[L] + 2 * (size_t)DO * 128, Wr[L] + 2 * (size_t)DO * 128,
                bl[L] + 2 * DO, accDst[L], stA[pL], stA[pL] + 128,
                pAs, pAq, gA, bA, invA, relu);
    }

    // --- classifier head on accounts (fused final BN, no relu) ---
    classifier_kernel<<<(nacc + 7) / 8, 256>>>(ya, nacc, clfW1, clfb1, clfW2, clfb2, out,
                                               stA[0], stA[0] + 128,
                                               bng[2], bnb[2], invA);
}

// round 9
// speedup vs baseline: 1.2475x; 1.2475x over previous
#include <cuda_runtime.h>
#include <math.h>
#include <stdint.h>

#define NACC_MAX 200000
#define NMER_MAX 100000
#define E_MAX    500000

// ---------------- scratch (device globals; no allocations allowed) -------------
__device__ float g_xa[(size_t)NACC_MAX * 128];
__device__ float g_xm[(size_t)NMER_MAX * 128];
__device__ float g_ya[(size_t)NACC_MAX * 128];
__device__ float g_ym[(size_t)NMER_MAX * 128];
__device__ float g_agg[(size_t)NACC_MAX * 128];   // rev -> acc
__device__ float g_agg2[(size_t)NACC_MAX * 128];  // transfer -> acc
__device__ float g_aggm[(size_t)NMER_MAX * 128];  // pays -> mer
__device__ int   g_rowptr[3][NACC_MAX + 1];
__device__ int   g_csr[3][E_MAX];
__device__ int   g_deg[3][NACC_MAX];
__device__ int   g_cur[3][NACC_MAX];
__device__ int   g_bsum[3][1024];
__device__ float g_stat[4 * 128];   // [sum_a | sqs_a | sum_m | sqs_m]

// ---------------- bf16x3 emulation helpers ---------------------------------------
__device__ __forceinline__ void split2(float2 v, uint32_t& h, uint32_t& l) {
    uint32_t u0 = __float_as_uint(v.x), u1 = __float_as_uint(v.y);
    h = __byte_perm(u0, u1, 0x7632);
    float r0 = v.x - __uint_as_float(u0 & 0xFFFF0000u);
    float r1 = v.y - __uint_as_float(u1 & 0xFFFF0000u);
    asm("cvt.rn.bf16x2.f32 %0, %1, %2;" : "=r"(l) : "f"(r1), "f"(r0));
}

__device__ __forceinline__ void mma_bf16(float* d, const uint32_t* a,
                                         uint32_t b0, uint32_t b1) {
    asm volatile(
        "mma.sync.aligned.m16n8k16.row.col.f32.bf16.bf16.f32 "
        "{%0,%1,%2,%3}, {%4,%5,%6,%7}, {%8,%9}, {%0,%1,%2,%3};"
        : "+f"(d[0]), "+f"(d[1]), "+f"(d[2]), "+f"(d[3])
        : "r"(a[0]), "r"(a[1]), "r"(a[2]), "r"(a[3]), "r"(b0), "r"(b1));
}

__device__ __forceinline__ uint32_t saddr(const void* p) {
    uint32_t a;
    asm("{ .reg .u64 t; cvta.to.shared.u64 t, %1; cvt.u32.u64 %0, t; }"
        : "=r"(a) : "l"(p));
    return a;
}

__device__ __forceinline__ void cp16(uint32_t dst, const void* src, bool pred) {
    asm volatile("cp.async.cg.shared.global [%0], [%1], 16, %2;"
                 :: "r"(dst), "l"(src), "r"(pred ? 16 : 0) : "memory");
}
__device__ __forceinline__ void cp_commit() {
    asm volatile("cp.async.commit_group;" ::: "memory");
}

// ---------------- CSR build ------------------------------------------------------
__global__ void hist_kernel(const int* __restrict__ ei, int E, int* __restrict__ deg) {
    int e = blockIdx.x * blockDim.x + threadIdx.x;
    if (e >= E) return;
    atomicAdd(&deg[ei[E + e]], 1);
}

__global__ void scan1(const int* __restrict__ deg, int n,
                      int* __restrict__ rowptr, int* __restrict__ bsum) {
    __shared__ int s[1024];
    int i = blockIdx.x * 1024 + threadIdx.x;
    int v = (i < n) ? deg[i] : 0;
    s[threadIdx.x] = v;
    __syncthreads();
    for (int off = 1; off < 1024; off <<= 1) {
        int t = (threadIdx.x >= off) ? s[threadIdx.x - off] : 0;
        __syncthreads();
        s[threadIdx.x] += t;
        __syncthreads();
    }
    if (i < n) rowptr[i + 1] = s[threadIdx.x];
    if (threadIdx.x == 1023) bsum[blockIdx.x] = s[1023];
}

__global__ void scan2(int* __restrict__ bsum, int nb) {
    __shared__ int s[1024];
    int v = (threadIdx.x < nb) ? bsum[threadIdx.x] : 0;
    s[threadIdx.x] = v;
    __syncthreads();
    for (int off = 1; off < 1024; off <<= 1) {
        int t = (threadIdx.x >= off) ? s[threadIdx.x - off] : 0;
        __syncthreads();
        s[threadIdx.x] += t;
        __syncthreads();
    }
    if (threadIdx.x < nb) bsum[threadIdx.x] = s[threadIdx.x] - v;  // exclusive
}

__global__ void scan3(int n, int* __restrict__ rowptr, const int* __restrict__ bsum) {
    int i = blockIdx.x * blockDim.x + threadIdx.x;
    if (i < n) rowptr[i + 1] += bsum[i >> 10];
    if (i == 0) rowptr[0] = 0;
}

__global__ void scatter_kernel(const int* __restrict__ ei, int E,
                               int* __restrict__ cur, int* __restrict__ csr) {
    int e = blockIdx.x * blockDim.x + threadIdx.x;
    if (e >= E) return;
    int src = ei[e], dst = ei[E + e];
    int pos = atomicAdd(&cur[dst], 1);
    csr[pos] = src;
}

// ---------------- fused mean aggregation: all edge types, warp per dst ----------
__global__ __launch_bounds__(256)
void agg_all(int n0, const int* __restrict__ rp0, const int* __restrict__ cs0,
             const float* __restrict__ src0, float* __restrict__ out0,
             int n1, const int* __restrict__ rp1, const int* __restrict__ cs1,
             const float* __restrict__ src1, float* __restrict__ out1,
             int n2, const int* __restrict__ rp2, const int* __restrict__ cs2,
             const float* __restrict__ src2, float* __restrict__ out2)
{
    int w = (blockIdx.x * blockDim.x + threadIdx.x) >> 5;
    int lane = threadIdx.x & 31;
    const int *rp, *cs; const float* src; float* out; int d;
    if (w < n0)           { rp = rp0; cs = cs0; src = src0; out = out0; d = w; }
    else if (w < n0 + n1) { rp = rp1; cs = cs1; src = src1; out = out1; d = w - n0; }
    else if (w < n0 + n1 + n2) { rp = rp2; cs = cs2; src = src2; out = out2; d = w - n0 - n1; }
    else return;

    int s = __ldg(&rp[d]), e = __ldg(&rp[d + 1]);
    float4 acc = make_float4(0.f, 0.f, 0.f, 0.f);
    int i = s;
    for (; i + 2 <= e; i += 2) {
        int s0 = __ldg(&cs[i]), s1 = __ldg(&cs[i + 1]);
        float4 v0 = __ldg(reinterpret_cast<const float4*>(src + (size_t)s0 * 128) + lane);
        float4 v1 = __ldg(reinterpret_cast<const float4*>(src + (size_t)s1 * 128) + lane);
        acc.x += v0.x + v1.x; acc.y += v0.y + v1.y;
        acc.z += v0.z + v1.z; acc.w += v0.w + v1.w;
    }
    if (i < e) {
        int s0 = __ldg(&cs[i]);
        float4 v0 = __ldg(reinterpret_cast<const float4*>(src + (size_t)s0 * 128) + lane);
        acc.x += v0.x; acc.y += v0.y; acc.z += v0.z; acc.w += v0.w;
    }
    float inv = 1.f / fmaxf((float)(e - s), 1.f);
    acc.x *= inv; acc.y *= inv; acc.z *= inv; acc.w *= inv;
    *(reinterpret_cast<float4*>(out + (size_t)d * 128) + lane) = acc;
}

// ---------------- bf16x3 pipelined GEMM (R5 compute, 3-stage cp.async) ----------
// D[128, DO] per CTA = A[128, K] @ B[DO, K]^T, fp32-accurate via hi/lo bf16 split:
//   d += ah*bh + ah*bl + al*bh
// MODE 0: A = A1[n,K] (input projection), epilogue = +bias.
// MODE 1: K=256, A = [mean_agg | xdst], B = [Wl | Wr]; epilogue = +bias,
//         row L2-normalize, optional += into C (HeteroConv sum).
// STATS : fused BatchNorm column sum/sumsq on final values.
// 512 threads = 16 warps, 4(m) x 4(n); warp tile 32m x (DO/4)n; BK=16.
// 3-stage cp.async pipeline in dynamic smem; compute identical to the R5 kernel.
#define TILE_F 2560            // 128*20 floats per tile buffer
#define SMEM_GEMM ((6 * TILE_F + 512) * 4)

template<int DO, int MODE, bool ACCUM, bool STATS>
__global__ __launch_bounds__(512)
void mma_gemm(int n, int K,
              const float* __restrict__ A1, const float* __restrict__ A2,
              const float* __restrict__ B1, const float* __restrict__ B2,
              const float* __restrict__ bias, float* __restrict__ C,
              float* __restrict__ gsum, float* __restrict__ gsqs)
{
    constexpr int NJ = DO / 32;
    extern __shared__ float smf[];
    float* AsBase = smf;                   // [3][128][20]
    float* BsBase = smf + 3 * TILE_F;      // [3][128][20]
    float* sBias  = smf + 6 * TILE_F;      // 128
    float* ssRow  = sBias + 128;           // 128
    float* sCS    = ssRow + 128;           // 128
    float* sCQ    = sCS + 128;             // 128

    int tid = threadIdx.x, lane = tid & 31, warp = tid >> 5;
    int g = lane >> 2, t = lane & 3;
    int wm = warp & 3, wn = warp >> 2;
    int row0 = blockIdx.x * 128;

    if (tid < DO) {
        sBias[tid] = bias[tid];
        if (STATS) { sCS[tid] = 0.f; sCQ[tid] = 0.f; }
    }
    if (tid < 128) ssRow[tid] = 0.f;

    float acc[2][NJ][4];
#pragma unroll
    for (int i = 0; i < 2; i++)
#pragma unroll
        for (int j = 0; j < NJ; j++)
#pragma unroll
            for (int c = 0; c < 4; c++) acc[i][j][c] = 0.f;

    const int T = K >> 4;

    auto load_tile = [&](int kt, int buf) {
        {   // A tile 128x16: one float4 per thread
            int m = tid >> 2, q = tid & 3, k = kt * 16 + q * 4;
            int r = row0 + m;
            bool p = (r < n);
            int rc = p ? r : 0;
            const float* src;
            if (MODE == 0) src = A1 + (size_t)rc * K + k;
            else src = (k < 128) ? A1 + (size_t)rc * 128 + k
                                 : A2 + (size_t)rc * 128 + (k - 128);
            cp16(saddr(AsBase + buf * TILE_F + m * 20 + q * 4), src, p);
        }
        if (tid < DO * 4) {  // B tile: DO*4 float4 <= 512 threads
            int j = tid >> 2, q = tid & 3, k = kt * 16 + q * 4;
            const float* src;
            if (MODE == 1) src = (k < 128) ? B1 + (size_t)j * 128 + k
                                           : B2 + (size_t)j * 128 + (k - 128);
            else src = B1 + (size_t)j * K + k;
            cp16(saddr(BsBase + buf * TILE_F + j * 20 + q * 4), src, true);
        }
    };

    // compute: byte-identical logic to the proven R5 kernel
    auto compute = [&](int buf) {
        const float* As = AsBase + buf * TILE_F;
        const float* Bs = BsBase + buf * TILE_F;
        uint32_t ah[2][4], al[2][4];
#pragma unroll
        for (int i = 0; i < 2; i++) {
            int rb = wm * 32 + i * 16;
            float2 v0 = *reinterpret_cast<const float2*>(As + (rb + g) * 20 + 2 * t);
            float2 v1 = *reinterpret_cast<const float2*>(As + (rb + g + 8) * 20 + 2 * t);
            float2 v2 = *reinterpret_cast<const float2*>(As + (rb + g) * 20 + 2 * t + 8);
            float2 v3 = *reinterpret_cast<const float2*>(As + (rb + g + 8) * 20 + 2 * t + 8);
            split2(v0, ah[i][0], al[i][0]);
            split2(v1, ah[i][1], al[i][1]);
            split2(v2, ah[i][2], al[i][2]);
            split2(v3, ah[i][3], al[i][3]);
        }
#pragma unroll
        for (int j = 0; j < NJ; j++) {
            int nb = wn * (NJ * 8) + j * 8 + g;
            float2 w0 = *reinterpret_cast<const float2*>(Bs + nb * 20 + 2 * t);
            float2 w1 = *reinterpret_cast<const float2*>(Bs + nb * 20 + 2 * t + 8);
            uint32_t bh0, bl0, bh1, bl1;
            split2(w0, bh0, bl0);
            split2(w1, bh1, bl1);
#pragma unroll
            for (int i = 0; i < 2; i++) {
                uint32_t bh[2] = {bh0, bh1}, bl[2] = {bl0, bl1};
                mma_bf16(acc[i][j], ah[i], bh[0], bh[1]);
                mma_bf16(acc[i][j], ah[i], bl[0], bl[1]);
                mma_bf16(acc[i][j], al[i], bh[0], bh[1]);
            }
        }
    };

    // 3-stage pipeline: prefetch issued AFTER the sync (safe: targets the buffer
    // whose compute finished last iteration), one tile deeper than R5.
    load_tile(0, 0); cp_commit();
    if (T > 1) { load_tile(1, 1); cp_commit(); }
    for (int kt = 0; kt < T; kt++) {
        if (kt + 1 < T) asm volatile("cp.async.wait_group 1;" ::: "memory");
        else            asm volatile("cp.async.wait_group 0;" ::: "memory");
        __syncthreads();
        if (kt + 2 < T) { load_tile(kt + 2, (kt + 2) % 3); cp_commit(); }
        compute(kt % 3);
        __syncthreads();
    }

    // ---- epilogue: bias, row L2-norm, accumulate, fused BN stats (R5 verbatim) --
#pragma unroll
    for (int i = 0; i < 2; i++) {
        float ss0 = 0.f, ss1 = 0.f;
#pragma unroll
        for (int j = 0; j < NJ; j++) {
            int cb = wn * (NJ * 8) + j * 8 + t * 2;
            float b0 = sBias[cb], b1 = sBias[cb + 1];
            acc[i][j][0] += b0; acc[i][j][1] += b1;
            acc[i][j][2] += b0; acc[i][j][3] += b1;
            if (MODE == 1) {
                ss0 += acc[i][j][0] * acc[i][j][0] + acc[i][j][1] * acc[i][j][1];
                ss1 += acc[i][j][2] * acc[i][j][2] + acc[i][j][3] * acc[i][j][3];
            }
        }
        if (MODE == 1) {
            ss0 += __shfl_xor_sync(0xffffffffu, ss0, 1);
            ss0 += __shfl_xor_sync(0xffffffffu, ss0, 2);
            ss1 += __shfl_xor_sync(0xffffffffu, ss1, 1);
            ss1 += __shfl_xor_sync(0xffffffffu, ss1, 2);
            if (t == 0) {
                atomicAdd(&ssRow[wm * 32 + i * 16 + g], ss0);
                atomicAdd(&ssRow[wm * 32 + i * 16 + g + 8], ss1);
            }
        }
    }
    __syncthreads();

    float cs[NJ][2], cq[NJ][2];
    if (STATS) {
#pragma unroll
        for (int j = 0; j < NJ; j++) { cs[j][0] = cs[j][1] = cq[j][0] = cq[j][1] = 0.f; }
    }

#pragma unroll
    for (int i = 0; i < 2; i++) {
        int rl = wm * 32 + i * 16 + g;
        float s0 = 1.f, s1 = 1.f;
        if (MODE == 1) {
            s0 = 1.f / fmaxf(sqrtf(ssRow[rl]), 1e-12f);
            s1 = 1.f / fmaxf(sqrtf(ssRow[rl + 8]), 1e-12f);
        }
        int r0 = row0 + rl, r1 = r0 + 8;
#pragma unroll
        for (int j = 0; j < NJ; j++) {
            int cb = wn * (NJ * 8) + j * 8 + t * 2;
            if (r0 < n) {
                float2* p = reinterpret_cast<float2*>(C + (size_t)r0 * DO + cb);
                float2 v = make_float2(acc[i][j][0] * s0, acc[i][j][1] * s0);
                if (ACCUM) { float2 o = *p; v.x += o.x; v.y += o.y; }
                *p = v;
                if (STATS) {
                    cs[j][0] += v.x; cs[j][1] += v.y;
                    cq[j][0] += v.x * v.x; cq[j][1] += v.y * v.y;
                }
            }
            if (r1 < n) {
                float2* p = reinterpret_cast<float2*>(C + (size_t)r1 * DO + cb);
                float2 v = make_float2(acc[i][j][2] * s1, acc[i][j][3] * s1);
                if (ACCUM) { float2 o = *p; v.x += o.x; v.y += o.y; }
                *p = v;
                if (STATS) {
                    cs[j][0] += v.x; cs[j][1] += v.y;
                    cq[j][0] += v.x * v.x; cq[j][1] += v.y * v.y;
                }
            }
        }
    }

    if (STATS) {
#pragma unroll
        for (int j = 0; j < NJ; j++)
#pragma unroll
            for (int c = 0; c < 2; c++) {
                float s = cs[j][c], q = cq[j][c];
                s += __shfl_xor_sync(0xffffffffu, s, 4);
                s += __shfl_xor_sync(0xffffffffu, s, 8);
                s += __shfl_xor_sync(0xffffffffu, s, 16);
                q += __shfl_xor_sync(0xffffffffu, q, 4);
                q += __shfl_xor_sync(0xffffffffu, q, 8);
                q += __shfl_xor_sync(0xffffffffu, q, 16);
                if (g == 0) {
                    int cb = wn * (NJ * 8) + j * 8 + t * 2 + c;
                    atomicAdd(&sCS[cb], s);
                    atomicAdd(&sCQ[cb], q);
                }
            }
        __syncthreads();
        if (tid < DO) {
            atomicAdd(&gsum[tid], sCS[tid]);
            atomicAdd(&gsqs[tid], sCQ[tid]);
        }
    }
}

// ---------------- BatchNorm apply (stats precomputed) ---------------------------
__global__ void bn_apply_kernel(const float* __restrict__ X, float* __restrict__ Y,
                                int n, int d,
                                const float* __restrict__ sum, const float* __restrict__ sqs,
                                const float* __restrict__ g, const float* __restrict__ b,
                                int relu)
{
    int d4 = d >> 2;
    size_t total = (size_t)n * d4;
    float invn = 1.f / (float)n;
    for (size_t i = blockIdx.x * (size_t)blockDim.x + threadIdx.x; i < total;
         i += (size_t)gridDim.x * blockDim.x) {
        int c = (int)(i % d4) * 4;
        float4 x = *(reinterpret_cast<const float4*>(X) + i);
        float4 y;
#pragma unroll
        for (int k = 0; k < 4; k++) {
            float mu = sum[c + k] * invn;
            float var = sqs[c + k] * invn - mu * mu;
            float xv = (&x.x)[k];
            float yv = (xv - mu) * rsqrtf(var + 1e-5f) * g[c + k] + b[c + k];
            if (relu) yv = fmaxf(yv, 0.f);
            (&y.x)[k] = yv;
        }
        *(reinterpret_cast<float4*>(Y) + i) = y;
    }
}

// ---------------- fused classifier: relu(x@W1^T+b1)@W2^T+b2 --------------------
__global__ __launch_bounds__(256)
void classifier_kernel(const float* __restrict__ X, int n,
                       const float* __restrict__ W1, const float* __restrict__ b1,
                       const float* __restrict__ W2, const float* __restrict__ b2,
                       float* __restrict__ out)
{
    __shared__ float sW1[64 * 65];
    __shared__ float sW2[64];
    __shared__ float sb1[64];
    int tid = threadIdx.x;
    for (int i = tid; i < 64 * 64; i += 256) {
        int j = i >> 6, k = i & 63;
        sW1[j * 65 + k] = W1[i];
    }
    if (tid < 64) { sW2[tid] = W2[tid]; sb1[tid] = b1[tid]; }
    __syncthreads();

    int lane = tid & 31;
    int row = blockIdx.x * 8 + (tid >> 5);
    if (row >= n) return;
    float x0 = X[(size_t)row * 64 + lane];
    float x1 = X[(size_t)row * 64 + 32 + lane];
    float h0 = sb1[lane], h1 = sb1[lane + 32];
#pragma unroll
    for (int k = 0; k < 32; k++) {
        float xk = __shfl_sync(0xffffffffu, x0, k);
        h0 += xk * sW1[lane * 65 + k];
        h1 += xk * sW1[(lane + 32) * 65 + k];
    }
#pragma unroll
    for (int k = 0; k < 32; k++) {
        float xk = __shfl_sync(0xffffffffu, x1, k);
        h0 += xk * sW1[lane * 65 + 32 + k];
        h1 += xk * sW1[(lane + 32) * 65 + 32 + k];
    }
    h0 = fmaxf(h0, 0.f); h1 = fmaxf(h1, 0.f);
    float p = h0 * sW2[lane] + h1 * sW2[lane + 32];
#pragma unroll
    for (int off = 16; off; off >>= 1)
        p += __shfl_xor_sync(0xffffffffu, p, off);
    if (lane == 0) out[row] = p + b2[0];
}

// ---------------- kernel_launch -------------------------------------------------
extern "C" void kernel_launch(void* const* d_in, const int* in_sizes, int n_in,
                              void* d_out, int out_size)
{
    const float* x_acc      = (const float*)d_in[0];
    const float* x_mer      = (const float*)d_in[1];
    const int*   ei[3]      = {(const int*)d_in[2], (const int*)d_in[3], (const int*)d_in[4]};
    const float* projW_acc  = (const float*)d_in[5];
    const float* projb_acc  = (const float*)d_in[6];
    const float* projW_mer  = (const float*)d_in[7];
    const float* projb_mer  = (const float*)d_in[8];
    const float* Wl[3] = {(const float*)d_in[9],  (const float*)d_in[12], (const float*)d_in[15]};
    const float* bl[3] = {(const float*)d_in[10], (const float*)d_in[13], (const float*)d_in[16]};
    const float* Wr[3] = {(const float*)d_in[11], (const float*)d_in[14], (const float*)d_in[17]};
    const float* bng[3] = {(const float*)d_in[18], (const float*)d_in[20], (const float*)d_in[22]};
    const float* bnb[3] = {(const float*)d_in[19], (const float*)d_in[21], (const float*)d_in[23]};
    const float* clfW1 = (const float*)d_in[24];
    const float* clfb1 = (const float*)d_in[25];
    const float* clfW2 = (const float*)d_in[26];
    const float* clfb2 = (const float*)d_in[27];
    float* out = (float*)d_out;

    int nacc = in_sizes[0] / 64;
    int nmer = in_sizes[1] / 32;
    int E    = in_sizes[2] / 2;

    float *xa, *xm, *ya, *ym, *agg, *agg2, *aggm, *stat;
    int *rowptr, *csr, *deg, *cur, *bsum;
    cudaGetSymbolAddress((void**)&xa,     g_xa);
    cudaGetSymbolAddress((void**)&xm,     g_xm);
    cudaGetSymbolAddress((void**)&ya,     g_ya);
    cudaGetSymbolAddress((void**)&ym,     g_ym);
    cudaGetSymbolAddress((void**)&agg,    g_agg);
    cudaGetSymbolAddress((void**)&agg2,   g_agg2);
    cudaGetSymbolAddress((void**)&aggm,   g_aggm);
    cudaGetSymbolAddress((void**)&stat,   g_stat);
    cudaGetSymbolAddress((void**)&rowptr, g_rowptr);
    cudaGetSymbolAddress((void**)&csr,    g_csr);
    cudaGetSymbolAddress((void**)&deg,    g_deg);
    cudaGetSymbolAddress((void**)&cur,    g_cur);
    cudaGetSymbolAddress((void**)&bsum,   g_bsum);

    int* rp[3]  = {rowptr, rowptr + (NACC_MAX + 1), rowptr + 2 * (NACC_MAX + 1)};
    int* cs3[3] = {csr, csr + E_MAX, csr + 2 * E_MAX};
    int* dg[3]  = {deg, deg + NACC_MAX, deg + 2 * NACC_MAX};
    int* cu[3]  = {cur, cur + NACC_MAX, cur + 2 * NACC_MAX};
    int* bs[3]  = {bsum, bsum + 1024, bsum + 2 * 1024};
    int ndst[3] = {nmer, nacc, nacc};
    float* sum_a = stat;        float* sqs_a = stat + 128;
    float* sum_m = stat + 256;  float* sqs_m = stat + 384;

    // dynamic smem opt-in for all GEMM instantiations
    cudaFuncSetAttribute(mma_gemm<128, 0, false, false>, cudaFuncAttributeMaxDynamicSharedMemorySize, SMEM_GEMM);
    cudaFuncSetAttribute(mma_gemm<128, 1, false, true >, cudaFuncAttributeMaxDynamicSharedMemorySize, SMEM_GEMM);
    cudaFuncSetAttribute(mma_gemm<128, 1, false, false>, cudaFuncAttributeMaxDynamicSharedMemorySize, SMEM_GEMM);
    cudaFuncSetAttribute(mma_gemm<128, 1, true,  true >, cudaFuncAttributeMaxDynamicSharedMemorySize, SMEM_GEMM);
    cudaFuncSetAttribute(mma_gemm<64,  1, false, false>, cudaFuncAttributeMaxDynamicSharedMemorySize, SMEM_GEMM);
    cudaFuncSetAttribute(mma_gemm<64,  1, true,  true >, cudaFuncAttributeMaxDynamicSharedMemorySize, SMEM_GEMM);

    int agrid = (nacc + 127) / 128;
    int mgrid = (nmer + 127) / 128;

    // --- input projections first (independent of CSR) ---
    mma_gemm<128, 0, false, false><<<agrid, 512, SMEM_GEMM>>>(nacc, 64, x_acc, nullptr,
        projW_acc, nullptr, projb_acc, xa, nullptr, nullptr);
    mma_gemm<128, 0, false, false><<<mgrid, 512, SMEM_GEMM>>>(nmer, 32, x_mer, nullptr,
        projW_mer, nullptr, projb_mer, xm, nullptr, nullptr);

    // --- CSR builds, phase-interleaved across the 3 edge types ---
    cudaMemsetAsync(deg, 0, 3 * (size_t)NACC_MAX * sizeof(int), 0);
    for (int t = 0; t < 3; t++)
        hist_kernel<<<(E + 255) / 256, 256>>>(ei[t], E, dg[t]);
    for (int t = 0; t < 3; t++)
        scan1<<<(ndst[t] + 1023) / 1024, 1024>>>(dg[t], ndst[t], rp[t], bs[t]);
    for (int t = 0; t < 3; t++)
        scan2<<<1, 1024>>>(bs[t], (ndst[t] + 1023) / 1024);
    for (int t = 0; t < 3; t++)
        scan3<<<(ndst[t] + 255) / 256, 256>>>(ndst[t], rp[t], bs[t]);
    for (int t = 0; t < 3; t++)
        cudaMemcpyAsync(cu[t], rp[t], (size_t)ndst[t] * sizeof(int),
                        cudaMemcpyDeviceToDevice, 0);
    for (int t = 0; t < 3; t++)
        scatter_kernel<<<(E + 255) / 256, 256>>>(ei[t], E, cu[t], cs3[t]);

    int douts[3] = {128, 128, 64};
    for (int L = 0; L < 3; L++) {
        int DO = douts[L];
        int n0 = (L < 2) ? nmer : 0;   // pays dead at L==2

        // --- all aggregations for this layer in one launch ---
        int twarp = n0 + nacc + nacc;
        agg_all<<<(twarp * 32 + 255) / 256, 256>>>(
            n0,   rp[0], cs3[0], xa, aggm,
            nacc, rp[1], cs3[1], xm, agg,
            nacc, rp[2], cs3[2], xa, agg2);

        // (a) pays: acc -> mer; emits merchant BN stats
        if (L < 2) {
            cudaMemsetAsync(sum_m, 0, 256 * sizeof(float), 0);
            mma_gemm<128, 1, false, true><<<mgrid, 512, SMEM_GEMM>>>(nmer, 256, aggm, xm,
                Wl[L] + 0 * (size_t)DO * 128, Wr[L] + 0 * (size_t)DO * 128,
                bl[L] + 0 * DO, ym, sum_m, sqs_m);
        }

        // (b) rev: mer -> acc (no stats: not final value yet)
        if (DO == 128)
            mma_gemm<128, 1, false, false><<<agrid, 512, SMEM_GEMM>>>(nacc, 256, agg, xa,
                Wl[L] + 1 * (size_t)DO * 128, Wr[L] + 1 * (size_t)DO * 128,
                bl[L] + 1 * DO, ya, nullptr, nullptr);
        else
            mma_gemm<64, 1, false, false><<<agrid, 512, SMEM_GEMM>>>(nacc, 256, agg, xa,
                Wl[L] + 1 * (size_t)DO * 128, Wr[L] + 1 * (size_t)DO * 128,
                bl[L] + 1 * DO, ya, nullptr, nullptr);

        // (c) transfer: acc -> acc (HeteroConv +=); emits account BN stats
        cudaMemsetAsync(sum_a, 0, 256 * sizeof(float), 0);
        if (DO == 128)
            mma_gemm<128, 1, true, true><<<agrid, 512, SMEM_GEMM>>>(nacc, 256, agg2, xa,
                Wl[L] + 2 * (size_t)DO * 128, Wr[L] + 2 * (size_t)DO * 128,
                bl[L] + 2 * DO, ya, sum_a, sqs_a);
        else
            mma_gemm<64, 1, true, true><<<agrid, 512, SMEM_GEMM>>>(nacc, 256, agg2, xa,
                Wl[L] + 2 * (size_t)DO * 128, Wr[L] + 2 * (size_t)DO * 128,
                bl[L] + 2 * DO, ya, sum_a, sqs_a);

        // (d) BN account (+ReLU except last layer)
        bn_apply_kernel<<<2048, 256>>>(ya, xa, nacc, DO, sum_a, sqs_a,
                                       bng[L] + 0 * DO, bnb[L] + 0 * DO, (L < 2) ? 1 : 0);

        // (e) BN merchant (+ReLU); dead at L==2
        if (L < 2) {
            bn_apply_kernel<<<2048, 256>>>(ym, xm, nmer, DO, sum_m, sqs_m,
                                           bng[L] + 1 * DO, bnb[L] + 1 * DO, 1);
        }
    }

    // --- classifier head on accounts ---
    classifier_kernel<<<(nacc + 7) / 8, 256>>>(xa, nacc, clfW1, clfb1, clfW2, clfb2, out);
}

// round 10
// speedup vs baseline: 1.2590x; 1.0093x over previous
#include <cuda_runtime.h>
#include <math.h>
#include <stdint.h>

#define NACC_MAX 200000
#define NMER_MAX 100000
#define E_MAX    500000

// ---------------- scratch (device globals; no allocations allowed) -------------
__device__ float    g_xa[(size_t)NACC_MAX * 128];
__device__ float    g_xm[(size_t)NMER_MAX * 128];
__device__ float    g_ya[(size_t)NACC_MAX * 128];
__device__ float    g_ym[(size_t)NMER_MAX * 128];
// pre-split bf16x2 hi/lo operand arrays ([n][64] uint32 = 64 k-pairs)
__device__ uint32_t g_aggh [(size_t)NACC_MAX * 64];   // rev -> acc
__device__ uint32_t g_aggl [(size_t)NACC_MAX * 64];
__device__ uint32_t g_agg2h[(size_t)NACC_MAX * 64];   // transfer -> acc
__device__ uint32_t g_agg2l[(size_t)NACC_MAX * 64];
__device__ uint32_t g_aggmh[(size_t)NMER_MAX * 64];   // pays -> mer
__device__ uint32_t g_aggml[(size_t)NMER_MAX * 64];
__device__ uint32_t g_xah[(size_t)NACC_MAX * 64];     // xdst split (accounts)
__device__ uint32_t g_xal[(size_t)NACC_MAX * 64];
__device__ uint32_t g_xmh[(size_t)NMER_MAX * 64];     // xdst split (merchants)
__device__ uint32_t g_xml[(size_t)NMER_MAX * 64];
__device__ uint32_t g_wh[128 * 128];                  // weight split scratch
__device__ uint32_t g_wl[128 * 128];
__device__ int   g_rowptr[3][NACC_MAX + 1];
__device__ int   g_csr[3][E_MAX];
__device__ int   g_deg[3][NACC_MAX];
__device__ int   g_cur[3][NACC_MAX];
__device__ int   g_bsum[3][1024];
__device__ float g_stat[4 * 128];   // [sum_a | sqs_a | sum_m | sqs_m]

// ---------------- bf16x3 emulation helpers ---------------------------------------
__device__ __forceinline__ void split2(float2 v, uint32_t& h, uint32_t& l) {
    uint32_t u0 = __float_as_uint(v.x), u1 = __float_as_uint(v.y);
    h = __byte_perm(u0, u1, 0x7632);
    float r0 = v.x - __uint_as_float(u0 & 0xFFFF0000u);
    float r1 = v.y - __uint_as_float(u1 & 0xFFFF0000u);
    asm("cvt.rn.bf16x2.f32 %0, %1, %2;" : "=r"(l) : "f"(r1), "f"(r0));
}

__device__ __forceinline__ void mma_bf16(float* d, const uint32_t* a,
                                         uint32_t b0, uint32_t b1) {
    asm volatile(
        "mma.sync.aligned.m16n8k16.row.col.f32.bf16.bf16.f32 "
        "{%0,%1,%2,%3}, {%4,%5,%6,%7}, {%8,%9}, {%0,%1,%2,%3};"
        : "+f"(d[0]), "+f"(d[1]), "+f"(d[2]), "+f"(d[3])
        : "r"(a[0]), "r"(a[1]), "r"(a[2]), "r"(a[3]), "r"(b0), "r"(b1));
}

__device__ __forceinline__ uint32_t saddr(const void* p) {
    uint32_t a;
    asm("{ .reg .u64 t; cvta.to.shared.u64 t, %1; cvt.u32.u64 %0, t; }"
        : "=r"(a) : "l"(p));
    return a;
}

__device__ __forceinline__ void cp16(uint32_t dst, const void* src, bool pred) {
    asm volatile("cp.async.cg.shared.global [%0], [%1], 16, %2;"
                 :: "r"(dst), "l"(src), "r"(pred ? 16 : 0) : "memory");
}
__device__ __forceinline__ void cp_commit() {
    asm volatile("cp.async.commit_group;" ::: "memory");
}

// ---------------- CSR build ------------------------------------------------------
__global__ void hist_kernel(const int* __restrict__ ei, int E, int* __restrict__ deg) {
    int e = blockIdx.x * blockDim.x + threadIdx.x;
    if (e >= E) return;
    atomicAdd(&deg[ei[E + e]], 1);
}

__global__ void scan1(const int* __restrict__ deg, int n,
                      int* __restrict__ rowptr, int* __restrict__ bsum) {
    __shared__ int s[1024];
    int i = blockIdx.x * 1024 + threadIdx.x;
    int v = (i < n) ? deg[i] : 0;
    s[threadIdx.x] = v;
    __syncthreads();
    for (int off = 1; off < 1024; off <<= 1) {
        int t = (threadIdx.x >= off) ? s[threadIdx.x - off] : 0;
        __syncthreads();
        s[threadIdx.x] += t;
        __syncthreads();
    }
    if (i < n) rowptr[i + 1] = s[threadIdx.x];
    if (threadIdx.x == 1023) bsum[blockIdx.x] = s[1023];
}

__global__ void scan2(int* __restrict__ bsum, int nb) {
    __shared__ int s[1024];
    int v = (threadIdx.x < nb) ? bsum[threadIdx.x] : 0;
    s[threadIdx.x] = v;
    __syncthreads();
    for (int off = 1; off < 1024; off <<= 1) {
        int t = (threadIdx.x >= off) ? s[threadIdx.x - off] : 0;
        __syncthreads();
        s[threadIdx.x] += t;
        __syncthreads();
    }
    if (threadIdx.x < nb) bsum[threadIdx.x] = s[threadIdx.x] - v;  // exclusive
}

__global__ void scan3(int n, int* __restrict__ rowptr, const int* __restrict__ bsum) {
    int i = blockIdx.x * blockDim.x + threadIdx.x;
    if (i < n) rowptr[i + 1] += bsum[i >> 10];
    if (i == 0) rowptr[0] = 0;
}

__global__ void scatter_kernel(const int* __restrict__ ei, int E,
                               int* __restrict__ cur, int* __restrict__ csr) {
    int e = blockIdx.x * blockDim.x + threadIdx.x;
    if (e >= E) return;
    int src = ei[e], dst = ei[E + e];
    int pos = atomicAdd(&cur[dst], 1);
    csr[pos] = src;
}

// ---------------- weight split: [Wl|Wr] fp32 -> packed bf16x2 hi/lo --------------
__global__ void split_w(const float* __restrict__ W1, const float* __restrict__ W2,
                        uint32_t* __restrict__ Bh, uint32_t* __restrict__ Bl, int DO)
{
    int idx = blockIdx.x * 256 + threadIdx.x;
    if (idx >= DO * 128) return;
    int j = idx >> 7, p = idx & 127;           // p = k-pair 0..127 over K=256
    const float* W = (p < 64) ? W1 + (size_t)j * 128 + 2 * p
                              : W2 + (size_t)j * 128 + 2 * (p - 64);
    uint32_t h, l;
    split2(make_float2(W[0], W[1]), h, l);
    Bh[idx] = h; Bl[idx] = l;
}

// ---------------- fused mean aggregation: writes pre-split hi/lo ----------------
__global__ __launch_bounds__(256)
void agg_all(int n0, const int* __restrict__ rp0, const int* __restrict__ cs0,
             const float* __restrict__ src0, uint32_t* __restrict__ oh0, uint32_t* __restrict__ ol0,
             int n1, const int* __restrict__ rp1, const int* __restrict__ cs1,
             const float* __restrict__ src1, uint32_t* __restrict__ oh1, uint32_t* __restrict__ ol1,
             int n2, const int* __restrict__ rp2, const int* __restrict__ cs2,
             const float* __restrict__ src2, uint32_t* __restrict__ oh2, uint32_t* __restrict__ ol2)
{
    int w = (blockIdx.x * blockDim.x + threadIdx.x) >> 5;
    int lane = threadIdx.x & 31;
    const int *rp, *cs; const float* src; uint32_t *oh, *ol; int d;
    if (w < n0)           { rp = rp0; cs = cs0; src = src0; oh = oh0; ol = ol0; d = w; }
    else if (w < n0 + n1) { rp = rp1; cs = cs1; src = src1; oh = oh1; ol = ol1; d = w - n0; }
    else if (w < n0 + n1 + n2) { rp = rp2; cs = cs2; src = src2; oh = oh2; ol = ol2; d = w - n0 - n1; }
    else return;

    int s = __ldg(&rp[d]), e = __ldg(&rp[d + 1]);
    float4 acc = make_float4(0.f, 0.f, 0.f, 0.f);
    int i = s;
    for (; i + 2 <= e; i += 2) {
        int s0 = __ldg(&cs[i]), s1 = __ldg(&cs[i + 1]);
        float4 v0 = __ldg(reinterpret_cast<const float4*>(src + (size_t)s0 * 128) + lane);
        float4 v1 = __ldg(reinterpret_cast<const float4*>(src + (size_t)s1 * 128) + lane);
        acc.x += v0.x + v1.x; acc.y += v0.y + v1.y;
        acc.z += v0.z + v1.z; acc.w += v0.w + v1.w;
    }
    if (i < e) {
        int s0 = __ldg(&cs[i]);
        float4 v0 = __ldg(reinterpret_cast<const float4*>(src + (size_t)s0 * 128) + lane);
        acc.x += v0.x; acc.y += v0.y; acc.z += v0.z; acc.w += v0.w;
    }
    float inv = 1.f / fmaxf((float)(e - s), 1.f);
    acc.x *= inv; acc.y *= inv; acc.z *= inv; acc.w *= inv;
    uint32_t h0, l0, h1, l1;
    split2(make_float2(acc.x, acc.y), h0, l0);
    split2(make_float2(acc.z, acc.w), h1, l1);
    *reinterpret_cast<uint2*>(oh + (size_t)d * 64 + 2 * lane) = make_uint2(h0, h1);
    *reinterpret_cast<uint2*>(ol + (size_t)d * 64 + 2 * lane) = make_uint2(l0, l1);
}

// ---------------- pre-split bf16x3 GEMM (MODE1): zero-ALU mainloop ---------------
// D[128, DO] per CTA = A[128, 256] @ B[DO, 256]^T with A = [mean_agg | xdst],
// all operands pre-split into packed bf16x2 hi/lo arrays ([n][64] / [DO][128]).
// Epilogue = +bias, row L2-norm, optional += (HeteroConv), optional BN stats.
// smem tile uint32[128][20]: cols 0-7 hi pairs, 8-15 lo pairs, 16-19 pad
// (bank = (20g+c)%32 covers all 32 banks for the fragment pattern).
#define TILE_U 2560            // 128*20 uint32 per tile buffer
#define SMEM_GEMM ((6 * TILE_U + 512) * 4)

template<int DO, bool ACCUM, bool STATS>
__global__ __launch_bounds__(512)
void mma_gemm_ps(int n,
                 const uint32_t* __restrict__ Ah1, const uint32_t* __restrict__ Al1,
                 const uint32_t* __restrict__ Ah2, const uint32_t* __restrict__ Al2,
                 const uint32_t* __restrict__ Bh,  const uint32_t* __restrict__ Bl,
                 const float* __restrict__ bias, float* __restrict__ C,
                 float* __restrict__ gsum, float* __restrict__ gsqs)
{
    constexpr int NJ = DO / 32;
    extern __shared__ uint32_t smu[];
    uint32_t* AsBase = smu;                  // [3][128][20]
    uint32_t* BsBase = smu + 3 * TILE_U;     // [3][128][20]
    float* sBias = reinterpret_cast<float*>(smu + 6 * TILE_U);
    float* ssRow = sBias + 128;
    float* sCS   = ssRow + 128;
    float* sCQ   = sCS + 128;

    int tid = threadIdx.x, lane = tid & 31, warp = tid >> 5;
    int g = lane >> 2, t = lane & 3;
    int wm = warp & 3, wn = warp >> 2;
    int row0 = blockIdx.x * 128;

    if (tid < DO) {
        sBias[tid] = bias[tid];
        if (STATS) { sCS[tid] = 0.f; sCQ[tid] = 0.f; }
    }
    if (tid < 128) ssRow[tid] = 0.f;

    float acc[2][NJ][4];
#pragma unroll
    for (int i = 0; i < 2; i++)
#pragma unroll
        for (int j = 0; j < NJ; j++)
#pragma unroll
            for (int c = 0; c < 4; c++) acc[i][j][c] = 0.f;

    const int T = 16;   // K=256, BK=16

    auto load_tile = [&](int kt, int buf) {
        int m = tid >> 2, q = tid & 3;           // q: 0,1 = hi chunks; 2,3 = lo
        {   // A tile: per row 8 hi + 8 lo uint32 = 4 x 16B chunks
            bool isA2 = (kt >= 8);
            int pairBase = (isA2 ? kt - 8 : kt) * 8;
            const uint32_t* H = isA2 ? Ah2 : Ah1;
            const uint32_t* L = isA2 ? Al2 : Al1;
            int r = row0 + m;
            bool p = (r < n);
            int rc = p ? r : 0;
            const uint32_t* src = ((q < 2) ? H : L)
                                + (size_t)rc * 64 + pairBase + (q & 1) * 4;
            cp16(saddr(AsBase + buf * TILE_U + m * 20 + q * 4), src, p);
        }
        if (tid < DO * 4) {   // B tile
            int j = tid >> 2, qb = tid & 3;
            const uint32_t* src = ((qb < 2) ? Bh : Bl)
                                + (size_t)j * 128 + kt * 8 + (qb & 1) * 4;
            cp16(saddr(BsBase + buf * TILE_U + j * 20 + qb * 4), src, true);
        }
    };

    auto compute = [&](int buf) {
        const uint32_t* As = AsBase + buf * TILE_U;
        const uint32_t* Bs = BsBase + buf * TILE_U;
        uint32_t ah[2][4], al[2][4];
#pragma unroll
        for (int i = 0; i < 2; i++) {
            int rb = wm * 32 + i * 16;
            ah[i][0] = As[(rb + g) * 20 + t];
            ah[i][1] = As[(rb + g + 8) * 20 + t];
            ah[i][2] = As[(rb + g) * 20 + t + 4];
            ah[i][3] = As[(rb + g + 8) * 20 + t + 4];
            al[i][0] = As[(rb + g) * 20 + t + 8];
            al[i][1] = As[(rb + g + 8) * 20 + t + 8];
            al[i][2] = As[(rb + g) * 20 + t + 12];
            al[i][3] = As[(rb + g + 8) * 20 + t + 12];
        }
#pragma unroll
        for (int j = 0; j < NJ; j++) {
            int nb = wn * (NJ * 8) + j * 8 + g;
            uint32_t bh0 = Bs[nb * 20 + t];
            uint32_t bh1 = Bs[nb * 20 + t + 4];
            uint32_t bl0 = Bs[nb * 20 + t + 8];
            uint32_t bl1 = Bs[nb * 20 + t + 12];
#pragma unroll
            for (int i = 0; i < 2; i++) {
                mma_bf16(acc[i][j], ah[i], bh0, bh1);
                mma_bf16(acc[i][j], ah[i], bl0, bl1);
                mma_bf16(acc[i][j], al[i], bh0, bh1);
            }
        }
    };

    // 3-stage pipeline (R9 proven)
    load_tile(0, 0); cp_commit();
    load_tile(1, 1); cp_commit();
    for (int kt = 0; kt < T; kt++) {
        if (kt + 1 < T) asm volatile("cp.async.wait_group 1;" ::: "memory");
        else            asm volatile("cp.async.wait_group 0;" ::: "memory");
        __syncthreads();
        if (kt + 2 < T) { load_tile(kt + 2, (kt + 2) % 3); cp_commit(); }
        compute(kt % 3);
        __syncthreads();
    }

    // ---- epilogue: bias, row L2-norm, accumulate, fused BN stats ----
#pragma unroll
    for (int i = 0; i < 2; i++) {
        float ss0 = 0.f, ss1 = 0.f;
#pragma unroll
        for (int j = 0; j < NJ; j++) {
            int cb = wn * (NJ * 8) + j * 8 + t * 2;
            float b0 = sBias[cb], b1 = sBias[cb + 1];
            acc[i][j][0] += b0; acc[i][j][1] += b1;
            acc[i][j][2] += b0; acc[i][j][3] += b1;
            ss0 += acc[i][j][0] * acc[i][j][0] + acc[i][j][1] * acc[i][j][1];
            ss1 += acc[i][j][2] * acc[i][j][2] + acc[i][j][3] * acc[i][j][3];
        }
        ss0 += __shfl_xor_sync(0xffffffffu, ss0, 1);
        ss0 += __shfl_xor_sync(0xffffffffu, ss0, 2);
        ss1 += __shfl_xor_sync(0xffffffffu, ss1, 1);
        ss1 += __shfl_xor_sync(0xffffffffu, ss1, 2);
        if (t == 0) {
            atomicAdd(&ssRow[wm * 32 + i * 16 + g], ss0);
            atomicAdd(&ssRow[wm * 32 + i * 16 + g + 8], ss1);
        }
    }
    __syncthreads();

    float cs[NJ][2], cq[NJ][2];
    if (STATS) {
#pragma unroll
        for (int j = 0; j < NJ; j++) { cs[j][0] = cs[j][1] = cq[j][0] = cq[j][1] = 0.f; }
    }

#pragma unroll
    for (int i = 0; i < 2; i++) {
        int rl = wm * 32 + i * 16 + g;
        float s0 = 1.f / fmaxf(sqrtf(ssRow[rl]), 1e-12f);
        float s1 = 1.f / fmaxf(sqrtf(ssRow[rl + 8]), 1e-12f);
        int r0 = row0 + rl, r1 = r0 + 8;
#pragma unroll
        for (int j = 0; j < NJ; j++) {
            int cb = wn * (NJ * 8) + j * 8 + t * 2;
            if (r0 < n) {
                float2* p = reinterpret_cast<float2*>(C + (size_t)r0 * DO + cb);
                float2 v = make_float2(acc[i][j][0] * s0, acc[i][j][1] * s0);
                if (ACCUM) { float2 o = *p; v.x += o.x; v.y += o.y; }
                *p = v;
                if (STATS) {
                    cs[j][0] += v.x; cs[j][1] += v.y;
                    cq[j][0] += v.x * v.x; cq[j][1] += v.y * v.y;
                }
            }
            if (r1 < n) {
                float2* p = reinterpret_cast<float2*>(C + (size_t)r1 * DO + cb);
                float2 v = make_float2(acc[i][j][2] * s1, acc[i][j][3] * s1);
                if (ACCUM) { float2 o = *p; v.x += o.x; v.y += o.y; }
                *p = v;
                if (STATS) {
                    cs[j][0] += v.x; cs[j][1] += v.y;
                    cq[j][0] += v.x * v.x; cq[j][1] += v.y * v.y;
                }
            }
        }
    }

    if (STATS) {
#pragma unroll
        for (int j = 0; j < NJ; j++)
#pragma unroll
            for (int c = 0; c < 2; c++) {
                float s = cs[j][c], q = cq[j][c];
                s += __shfl_xor_sync(0xffffffffu, s, 4);
                s += __shfl_xor_sync(0xffffffffu, s, 8);
                s += __shfl_xor_sync(0xffffffffu, s, 16);
                q += __shfl_xor_sync(0xffffffffu, q, 4);
                q += __shfl_xor_sync(0xffffffffu, q, 8);
                q += __shfl_xor_sync(0xffffffffu, q, 16);
                if (g == 0) {
                    int cb = wn * (NJ * 8) + j * 8 + t * 2 + c;
                    atomicAdd(&sCS[cb], s);
                    atomicAdd(&sCQ[cb], q);
                }
            }
        __syncthreads();
        if (tid < DO) {
            atomicAdd(&gsum[tid], sCS[tid]);
            atomicAdd(&gsqs[tid], sCQ[tid]);
        }
    }
}

// ---------------- projection GEMM (MODE0, split-in-loop, R9 compute) -------------
// C[n,128] = A[n,K] @ W[128,K]^T + bias; also emits pre-split hi/lo of C.
__global__ __launch_bounds__(512)
void proj_gemm(int n, int K,
               const float* __restrict__ A1, const float* __restrict__ B1,
               const float* __restrict__ bias, float* __restrict__ C,
               uint32_t* __restrict__ Ch, uint32_t* __restrict__ Cl)
{
    constexpr int DO = 128, NJ = 4;
    extern __shared__ float smf[];
    float* AsBase = smf;
    float* BsBase = smf + 3 * TILE_U;
    float* sBias  = smf + 6 * TILE_U;

    int tid = threadIdx.x, lane = tid & 31, warp = tid >> 5;
    int g = lane >> 2, t = lane & 3;
    int wm = warp & 3, wn = warp >> 2;
    int row0 = blockIdx.x * 128;

    if (tid < DO) sBias[tid] = bias[tid];

    float acc[2][NJ][4];
#pragma unroll
    for (int i = 0; i < 2; i++)
#pragma unroll
        for (int j = 0; j < NJ; j++)
#pragma unroll
            for (int c = 0; c < 4; c++) acc[i][j][c] = 0.f;

    const int T = K >> 4;

    auto load_tile = [&](int kt, int buf) {
        {
            int m = tid >> 2, q = tid & 3, k = kt * 16 + q * 4;
            int r = row0 + m;
            bool p = (r < n);
            int rc = p ? r : 0;
            cp16(saddr(AsBase + buf * TILE_U + m * 20 + q * 4),
                 A1 + (size_t)rc * K + k, p);
        }
        {
            int j = tid >> 2, q = tid & 3, k = kt * 16 + q * 4;
            cp16(saddr(BsBase + buf * TILE_U + j * 20 + q * 4),
                 B1 + (size_t)j * K + k, true);
        }
    };

    auto compute = [&](int buf) {
        const float* As = AsBase + buf * TILE_U;
        const float* Bs = BsBase + buf * TILE_U;
        uint32_t ah[2][4], al[2][4];
#pragma unroll
        for (int i = 0; i < 2; i++) {
            int rb = wm * 32 + i * 16;
            float2 v0 = *reinterpret_cast<const float2*>(As + (rb + g) * 20 + 2 * t);
            float2 v1 = *reinterpret_cast<const float2*>(As + (rb + g + 8) * 20 + 2 * t);
            float2 v2 = *reinterpret_cast<const float2*>(As + (rb + g) * 20 + 2 * t + 8);
            float2 v3 = *reinterpret_cast<const float2*>(As + (rb + g + 8) * 20 + 2 * t + 8);
            split2(v0, ah[i][0], al[i][0]);
            split2(v1, ah[i][1], al[i][1]);
            split2(v2, ah[i][2], al[i][2]);
            split2(v3, ah[i][3], al[i][3]);
        }
#pragma unroll
        for (int j = 0; j < NJ; j++) {
            int nb = wn * (NJ * 8) + j * 8 + g;
            float2 w0 = *reinterpret_cast<const float2*>(Bs + nb * 20 + 2 * t);
            float2 w1 = *reinterpret_cast<const float2*>(Bs + nb * 20 + 2 * t + 8);
            uint32_t bh0, bl0, bh1, bl1;
            split2(w0, bh0, bl0);
            split2(w1, bh1, bl1);
#pragma unroll
            for (int i = 0; i < 2; i++) {
                mma_bf16(acc[i][j], ah[i], bh0, bh1);
                mma_bf16(acc[i][j], ah[i], bl0, bl1);
                mma_bf16(acc[i][j], al[i], bh0, bh1);
            }
        }
    };

    load_tile(0, 0); cp_commit();
    if (T > 1) { load_tile(1, 1); cp_commit(); }
    for (int kt = 0; kt < T; kt++) {
        if (kt + 1 < T) asm volatile("cp.async.wait_group 1;" ::: "memory");
        else            asm volatile("cp.async.wait_group 0;" ::: "memory");
        __syncthreads();
        if (kt + 2 < T) { load_tile(kt + 2, (kt + 2) % 3); cp_commit(); }
        compute(kt % 3);
        __syncthreads();
    }

    // epilogue: +bias, store fp32 + pre-split hi/lo
#pragma unroll
    for (int i = 0; i < 2; i++) {
        int rl = wm * 32 + i * 16 + g;
        int r0 = row0 + rl, r1 = r0 + 8;
#pragma unroll
        for (int j = 0; j < NJ; j++) {
            int cb = wn * (NJ * 8) + j * 8 + t * 2;
            float b0 = sBias[cb], b1 = sBias[cb + 1];
            if (r0 < n) {
                float2 v = make_float2(acc[i][j][0] + b0, acc[i][j][1] + b1);
                *reinterpret_cast<float2*>(C + (size_t)r0 * DO + cb) = v;
                uint32_t h, l; split2(v, h, l);
                Ch[(size_t)r0 * 64 + cb / 2] = h;
                Cl[(size_t)r0 * 64 + cb / 2] = l;
            }
            if (r1 < n) {
                float2 v = make_float2(acc[i][j][2] + b0, acc[i][j][3] + b1);
                *reinterpret_cast<float2*>(C + (size_t)r1 * DO + cb) = v;
                uint32_t h, l; split2(v, h, l);
                Ch[(size_t)r1 * 64 + cb / 2] = h;
                Cl[(size_t)r1 * 64 + cb / 2] = l;
            }
        }
    }
}

// ---------------- BatchNorm apply: fp32 out + pre-split hi/lo --------------------
__global__ void bn_apply_kernel(const float* __restrict__ X, float* __restrict__ Y,
                                uint32_t* __restrict__ Yh, uint32_t* __restrict__ Yl,
                                int n, int d,
                                const float* __restrict__ sum, const float* __restrict__ sqs,
                                const float* __restrict__ g, const float* __restrict__ b,
                                int relu)
{
    int d4 = d >> 2;
    size_t total = (size_t)n * d4;
    float invn = 1.f / (float)n;
    for (size_t i = blockIdx.x * (size_t)blockDim.x + threadIdx.x; i < total;
         i += (size_t)gridDim.x * blockDim.x) {
        int c = (int)(i % d4) * 4;
        float4 x = *(reinterpret_cast<const float4*>(X) + i);
        float4 y;
#pragma unroll
        for (int k = 0; k < 4; k++) {
            float mu = sum[c + k] * invn;
            float var = sqs[c + k] * invn - mu * mu;
            float xv = (&x.x)[k];
            float yv = (xv - mu) * rsqrtf(var + 1e-5f) * g[c + k] + b[c + k];
            if (relu) yv = fmaxf(yv, 0.f);
            (&y.x)[k] = yv;
        }
        *(reinterpret_cast<float4*>(Y) + i) = y;
        if (Yh) {
            uint32_t h0, l0, h1, l1;
            split2(make_float2(y.x, y.y), h0, l0);
            split2(make_float2(y.z, y.w), h1, l1);
            *reinterpret_cast<uint2*>(Yh + i * 2) = make_uint2(h0, h1);
            *reinterpret_cast<uint2*>(Yl + i * 2) = make_uint2(l0, l1);
        }
    }
}

// ---------------- fused classifier: relu(x@W1^T+b1)@W2^T+b2 --------------------
__global__ __launch_bounds__(256)
void classifier_kernel(const float* __restrict__ X, int n,
                       const float* __restrict__ W1, const float* __restrict__ b1,
                       const float* __restrict__ W2, const float* __restrict__ b2,
                       float* __restrict__ out)
{
    __shared__ float sW1[64 * 65];
    __shared__ float sW2[64];
    __shared__ float sb1[64];
    int tid = threadIdx.x;
    for (int i = tid; i < 64 * 64; i += 256) {
        int j = i >> 6, k = i & 63;
        sW1[j * 65 + k] = W1[i];
    }
    if (tid < 64) { sW2[tid] = W2[tid]; sb1[tid] = b1[tid]; }
    __syncthreads();

    int lane = tid & 31;
    int row = blockIdx.x * 8 + (tid >> 5);
    if (row >= n) return;
    float x0 = X[(size_t)row * 64 + lane];
    float x1 = X[(size_t)row * 64 + 32 + lane];
    float h0 = sb1[lane], h1 = sb1[lane + 32];
#pragma unroll
    for (int k = 0; k < 32; k++) {
        float xk = __shfl_sync(0xffffffffu, x0, k);
        h0 += xk * sW1[lane * 65 + k];
        h1 += xk * sW1[(lane + 32) * 65 + k];
    }
#pragma unroll
    for (int k = 0; k < 32; k++) {
        float xk = __shfl_sync(0xffffffffu, x1, k);
        h0 += xk * sW1[lane * 65 + 32 + k];
        h1 += xk * sW1[(lane + 32) * 65 + 32 + k];
    }
    h0 = fmaxf(h0, 0.f); h1 = fmaxf(h1, 0.f);
    float p = h0 * sW2[lane] + h1 * sW2[lane + 32];
#pragma unroll
    for (int off = 16; off; off >>= 1)
        p += __shfl_xor_sync(0xffffffffu, p, off);
    if (lane == 0) out[row] = p + b2[0];
}

// ---------------- kernel_launch -------------------------------------------------
extern "C" void kernel_launch(void* const* d_in, const int* in_sizes, int n_in,
                              void* d_out, int out_size)
{
    const float* x_acc      = (const float*)d_in[0];
    const float* x_mer      = (const float*)d_in[1];
    const int*   ei[3]      = {(const int*)d_in[2], (const int*)d_in[3], (const int*)d_in[4]};
    const float* projW_acc  = (const float*)d_in[5];
    const float* projb_acc  = (const float*)d_in[6];
    const float* projW_mer  = (const float*)d_in[7];
    const float* projb_mer  = (const float*)d_in[8];
    const float* Wl[3] = {(const float*)d_in[9],  (const float*)d_in[12], (const float*)d_in[15]};
    const float* bl[3] = {(const float*)d_in[10], (const float*)d_in[13], (const float*)d_in[16]};
    const float* Wr[3] = {(const float*)d_in[11], (const float*)d_in[14], (const float*)d_in[17]};
    const float* bng[3] = {(const float*)d_in[18], (const float*)d_in[20], (const float*)d_in[22]};
    const float* bnb[3] = {(const float*)d_in[19], (const float*)d_in[21], (const float*)d_in[23]};
    const float* clfW1 = (const float*)d_in[24];
    const float* clfb1 = (const float*)d_in[25];
    const float* clfW2 = (const float*)d_in[26];
    const float* clfb2 = (const float*)d_in[27];
    float* out = (float*)d_out;

    int nacc = in_sizes[0] / 64;
    int nmer = in_sizes[1] / 32;
    int E    = in_sizes[2] / 2;

    float *xa, *xm, *ya, *ym, *stat;
    uint32_t *aggh, *aggl, *agg2h, *agg2l, *aggmh, *aggml;
    uint32_t *xah, *xal, *xmh, *xml, *wh, *wl;
    int *rowptr, *csr, *deg, *cur, *bsum;
    cudaGetSymbolAddress((void**)&xa,     g_xa);
    cudaGetSymbolAddress((void**)&xm,     g_xm);
    cudaGetSymbolAddress((void**)&ya,     g_ya);
    cudaGetSymbolAddress((void**)&ym,     g_ym);
    cudaGetSymbolAddress((void**)&aggh,   g_aggh);
    cudaGetSymbolAddress((void**)&aggl,   g_aggl);
    cudaGetSymbolAddress((void**)&agg2h,  g_agg2h);
    cudaGetSymbolAddress((void**)&agg2l,  g_agg2l);
    cudaGetSymbolAddress((void**)&aggmh,  g_aggmh);
    cudaGetSymbolAddress((void**)&aggml,  g_aggml);
    cudaGetSymbolAddress((void**)&xah,    g_xah);
    cudaGetSymbolAddress((void**)&xal,    g_xal);
    cudaGetSymbolAddress((void**)&xmh,    g_xmh);
    cudaGetSymbolAddress((void**)&xml,    g_xml);
    cudaGetSymbolAddress((void**)&wh,     g_wh);
    cudaGetSymbolAddress((void**)&wl,     g_wl);
    cudaGetSymbolAddress((void**)&stat,   g_stat);
    cudaGetSymbolAddress((void**)&rowptr, g_rowptr);
    cudaGetSymbolAddress((void**)&csr,    g_csr);
    cudaGetSymbolAddress((void**)&deg,    g_deg);
    cudaGetSymbolAddress((void**)&cur,    g_cur);
    cudaGetSymbolAddress((void**)&bsum,   g_bsum);

    int* rp[3]  = {rowptr, rowptr + (NACC_MAX + 1), rowptr + 2 * (NACC_MAX + 1)};
    int* cs3[3] = {csr, csr + E_MAX, csr + 2 * E_MAX};
    int* dg[3]  = {deg, deg + NACC_MAX, deg + 2 * NACC_MAX};
    int* cu[3]  = {cur, cur + NACC_MAX, cur + 2 * NACC_MAX};
    int* bs[3]  = {bsum, bsum + 1024, bsum + 2 * 1024};
    int ndst[3] = {nmer, nacc, nacc};
    float* sum_a = stat;        float* sqs_a = stat + 128;
    float* sum_m = stat + 256;  float* sqs_m = stat + 384;

    // dynamic smem opt-in
    cudaFuncSetAttribute(proj_gemm, cudaFuncAttributeMaxDynamicSharedMemorySize, SMEM_GEMM);
    cudaFuncSetAttribute(mma_gemm_ps<128, false, true >, cudaFuncAttributeMaxDynamicSharedMemorySize, SMEM_GEMM);
    cudaFuncSetAttribute(mma_gemm_ps<128, false, false>, cudaFuncAttributeMaxDynamicSharedMemorySize, SMEM_GEMM);
    cudaFuncSetAttribute(mma_gemm_ps<128, true,  true >, cudaFuncAttributeMaxDynamicSharedMemorySize, SMEM_GEMM);
    cudaFuncSetAttribute(mma_gemm_ps<64,  false, false>, cudaFuncAttributeMaxDynamicSharedMemorySize, SMEM_GEMM);
    cudaFuncSetAttribute(mma_gemm_ps<64,  true,  true >, cudaFuncAttributeMaxDynamicSharedMemorySize, SMEM_GEMM);

    int agrid = (nacc + 127) / 128;
    int mgrid = (nmer + 127) / 128;

    // --- input projections (fp32 + split outputs) ---
    proj_gemm<<<agrid, 512, SMEM_GEMM>>>(nacc, 64, x_acc, projW_acc, projb_acc, xa, xah, xal);
    proj_gemm<<<mgrid, 512, SMEM_GEMM>>>(nmer, 32, x_mer, projW_mer, projb_mer, xm, xmh, xml);

    // --- CSR builds, phase-interleaved across the 3 edge types ---
    cudaMemsetAsync(deg, 0, 3 * (size_t)NACC_MAX * sizeof(int), 0);
    for (int t = 0; t < 3; t++)
        hist_kernel<<<(E + 255) / 256, 256>>>(ei[t], E, dg[t]);
    for (int t = 0; t < 3; t++)
        scan1<<<(ndst[t] + 1023) / 1024, 1024>>>(dg[t], ndst[t], rp[t], bs[t]);
    for (int t = 0; t < 3; t++)
        scan2<<<1, 1024>>>(bs[t], (ndst[t] + 1023) / 1024);
    for (int t = 0; t < 3; t++)
        scan3<<<(ndst[t] + 255) / 256, 256>>>(ndst[t], rp[t], bs[t]);
    for (int t = 0; t < 3; t++)
        cudaMemcpyAsync(cu[t], rp[t], (size_t)ndst[t] * sizeof(int),
                        cudaMemcpyDeviceToDevice, 0);
    for (int t = 0; t < 3; t++)
        scatter_kernel<<<(E + 255) / 256, 256>>>(ei[t], E, cu[t], cs3[t]);

    int douts[3] = {128, 128, 64};
    for (int L = 0; L < 3; L++) {
        int DO = douts[L];
        int n0 = (L < 2) ? nmer : 0;   // pays dead at L==2

        // --- all aggregations for this layer in one launch (pre-split outputs) ---
        int twarp = n0 + nacc + nacc;
        agg_all<<<(twarp * 32 + 255) / 256, 256>>>(
            n0,   rp[0], cs3[0], xa, aggmh, aggml,
            nacc, rp[1], cs3[1], xm, aggh,  aggl,
            nacc, rp[2], cs3[2], xa, agg2h, agg2l);

        // (a) pays: acc -> mer; emits merchant BN stats
        if (L < 2) {
            split_w<<<(DO * 128 + 255) / 256, 256>>>(
                Wl[L] + 0 * (size_t)DO * 128, Wr[L] + 0 * (size_t)DO * 128, wh, wl, DO);
            cudaMemsetAsync(sum_m, 0, 256 * sizeof(float), 0);
            mma_gemm_ps<128, false, true><<<mgrid, 512, SMEM_GEMM>>>(nmer,
                aggmh, aggml, xmh, xml, wh, wl,
                bl[L] + 0 * DO, ym, sum_m, sqs_m);
        }

        // (b) rev: mer -> acc (no stats)
        split_w<<<(DO * 128 + 255) / 256, 256>>>(
            Wl[L] + 1 * (size_t)DO * 128, Wr[L] + 1 * (size_t)DO * 128, wh, wl, DO);
        if (DO == 128)
            mma_gemm_ps<128, false, false><<<agrid, 512, SMEM_GEMM>>>(nacc,
                aggh, aggl, xah, xal, wh, wl, bl[L] + 1 * DO, ya, nullptr, nullptr);
        else
            mma_gemm_ps<64, false, false><<<agrid, 512, SMEM_GEMM>>>(nacc,
                aggh, aggl, xah, xal, wh, wl, bl[L] + 1 * DO, ya, nullptr, nullptr);

        // (c) transfer: acc -> acc (HeteroConv +=); emits account BN stats
        split_w<<<(DO * 128 + 255) / 256, 256>>>(
            Wl[L] + 2 * (size_t)DO * 128, Wr[L] + 2 * (size_t)DO * 128, wh, wl, DO);
        cudaMemsetAsync(sum_a, 0, 256 * sizeof(float), 0);
        if (DO == 128)
            mma_gemm_ps<128, true, true><<<agrid, 512, SMEM_GEMM>>>(nacc,
                agg2h, agg2l, xah, xal, wh, wl, bl[L] + 2 * DO, ya, sum_a, sqs_a);
        else
            mma_gemm_ps<64, true, true><<<agrid, 512, SMEM_GEMM>>>(nacc,
                agg2h, agg2l, xah, xal, wh, wl, bl[L] + 2 * DO, ya, sum_a, sqs_a);

        // (d) BN account (+ReLU except last layer); emits split xdst for next layer
        bn_apply_kernel<<<2048, 256>>>(ya, xa, (L < 2) ? xah : nullptr, (L < 2) ? xal : nullptr,
                                       nacc, DO, sum_a, sqs_a,
                                       bng[L] + 0 * DO, bnb[L] + 0 * DO, (L < 2) ? 1 : 0);

        // (e) BN merchant (+ReLU); dead at L==2
        if (L < 2) {
            bn_apply_kernel<<<2048, 256>>>(ym, xm, xmh, xml, nmer, DO, sum_m, sqs_m,
                                           bng[L] + 1 * DO, bnb[L] + 1 * DO, 1);
        }
    }

    // --- classifier head on accounts ---
    classifier_kernel<<<(nacc + 7) / 8, 256>>>(xa, nacc, clfW1, clfb1, clfW2, clfb2, out);
}